// round 5
// baseline (speedup 1.0000x reference)
#include <cuda_runtime.h>

// UniSURF-style renderer, lane-split: each ray is handled by a LANE PAIR.
// Lane h = lane&1 evaluates hidden units [16h, 16h+16) (8 packed f32x2 pairs);
// partial sums combine with one shfl_xor per MLP eval.
//   occ logit z(d) = b2 + sum_j relu(A_j + d*R_j) * W2_j
//   Coarse march uses only sign(z); packed fp32x2 FMAs; branchless crossing
//   bitmask + __ffs; grid-stride over ray-pairs with uniform trip count
//   (all shfls warp-converged); 5 blocks/SM for occupancy.

#define HID     32
#define LPAIR   8            // f32x2 pairs per lane (16 units)
#define NSTEPS  32
#define NSECANT 8
#define NEARV   0.5f
#define EPSV    1e-6f
#define NBLK    (148 * 5)    // 5 blocks/SM x 148 SMs (sm_100a)

typedef unsigned long long ull;

__device__ __forceinline__ ull pack2(float x, float y) {
    ull r;
    asm("mov.b64 %0, {%1, %2};" : "=l"(r) : "f"(x), "f"(y));
    return r;
}

__device__ __forceinline__ void unpack2(ull v, float& x, float& y) {
    asm("mov.b64 {%0, %1}, %2;" : "=f"(x), "=f"(y) : "l"(v));
}

// one hidden-unit pair: acc += relu(A + d*R) * W   (packed fp32x2)
__device__ __forceinline__ ull pair_step(ull dd, ull R, ull A, ull W, ull acc) {
    ull x;
    asm("fma.rn.f32x2 %0, %1, %2, %3;" : "=l"(x) : "l"(dd), "l"(R), "l"(A));
    float x0, x1;
    unpack2(x, x0, x1);
    x0 = fmaxf(x0, 0.0f);
    x1 = fmaxf(x1, 0.0f);
    ull h = pack2(x0, x1);
    ull out;
    asm("fma.rn.f32x2 %0, %1, %2, %3;" : "=l"(out) : "l"(h), "l"(W), "l"(acc));
    return out;
}

// half-MLP eval on this lane + shfl-combine with partner lane.
// Both lanes return the bitwise-identical full logit.
__device__ __forceinline__ float occ_z2(float d, const ull* R, const ull* A,
                                        const ull* W, float b2v) {
    ull dd;
    asm("mov.b64 %0, {%1, %1};" : "=l"(dd) : "f"(d));
    ull a0 = 0ull, a1 = 0ull, a2 = 0ull, a3 = 0ull;
    a0 = pair_step(dd, R[0], A[0], W[0], a0);
    a1 = pair_step(dd, R[1], A[1], W[1], a1);
    a2 = pair_step(dd, R[2], A[2], W[2], a2);
    a3 = pair_step(dd, R[3], A[3], W[3], a3);
    a0 = pair_step(dd, R[4], A[4], W[4], a0);
    a1 = pair_step(dd, R[5], A[5], W[5], a1);
    a2 = pair_step(dd, R[6], A[6], W[6], a2);
    a3 = pair_step(dd, R[7], A[7], W[7], a3);
    ull s01, s23, s;
    asm("add.rn.f32x2 %0, %1, %2;" : "=l"(s01) : "l"(a0), "l"(a1));
    asm("add.rn.f32x2 %0, %1, %2;" : "=l"(s23) : "l"(a2), "l"(a3));
    asm("add.rn.f32x2 %0, %1, %2;" : "=l"(s)   : "l"(s01), "l"(s23));
    float sx, sy;
    unpack2(s, sx, sy);
    const float loc = sx + sy;
    const float tot = loc + __shfl_xor_sync(0xffffffffu, loc, 1);
    return b2v + tot;
}

__device__ __forceinline__ float sigmoidf_(float z) {
    return 1.0f / (1.0f + __expf(-z));
}

__global__ void __launch_bounds__(128, 5) unisurf_kernel(
    const float* __restrict__ cam, const float* __restrict__ dirs,
    const float* __restrict__ W1, const float* __restrict__ b1,
    const float* __restrict__ W2, const float* __restrict__ b2,
    float* __restrict__ out, int P)
{
    __shared__ float sW1[3][HID];
    __shared__ float sA[HID];
    __shared__ float sW2[HID];
    __shared__ float sMisc[5];  // cam0..2, b2, |cam|^2

    const int tid = threadIdx.x;
    if (tid < HID) {
        const float c0 = cam[0], c1 = cam[1], c2 = cam[2];
        const float w0 = W1[tid], w1 = W1[HID + tid], w2 = W1[2 * HID + tid];
        sW1[0][tid] = w0;
        sW1[1][tid] = w1;
        sW1[2][tid] = w2;
        sA[tid] = fmaf(c0, w0, fmaf(c1, w1, fmaf(c2, w2, b1[tid])));
        sW2[tid] = W2[tid];
        if (tid == 0) {
            sMisc[0] = c0; sMisc[1] = c1; sMisc[2] = c2;
            sMisc[3] = b2[0];
            sMisc[4] = c0 * c0 + c1 * c1 + c2 * c2;
        }
    }
    __syncthreads();

    const int lane = tid & 31;
    const int half = lane & 1;
    const int jb = half * (HID / 2);             // unit base for this lane

    const int gthread = blockIdx.x * blockDim.x + tid;
    const int rstride = (gridDim.x * blockDim.x) >> 1;   // ray-pairs in flight
    const int ray0 = gthread >> 1;
    const int niter = (P + rstride - 1) / rstride;       // uniform trip count

    const float c0 = sMisc[0], c1 = sMisc[1], c2 = sMisc[2];
    const float b2v = sMisc[3], cc = sMisc[4];
    const float stepc = 1.0f / (float)(NSTEPS - 1);

    for (int it = 0; it < niter; ++it) {
        const int p = ray0 + it * rstride;
        const bool valid = p < P;
        if (__all_sync(0xffffffffu, !valid)) break;  // whole warp done
        const int pc = valid ? p : (P - 1);

        const float dx = dirs[3 * pc + 0];
        const float dy = dirs[3 * pc + 1];
        const float dz = dirs[3 * pc + 2];
        const float invn = rsqrtf(dx * dx + dy * dy + dz * dz);
        const float rx = dx * invn, ry = dy * invn, rz = dz * invn;

        const float rcd = rx * c0 + ry * c1 + rz * c2;
        const float under = rcd * rcd - (cc - 1.0f);   // radius = 1
        const bool hit = under > 0.0f;
        const float s = sqrtf(fmaxf(under, 0.0f));
        const float far = fmaxf(s - rcd, NEARV + EPSV);

        // this lane's half of the per-ray MLP operands (8 f32x2 pairs)
        ull R[LPAIR], A[LPAIR], W[LPAIR];
#pragma unroll
        for (int k = 0; k < LPAIR; k++) {
            const int j = jb + 2 * k;
            const float r0 = fmaf(rx, sW1[0][j],
                             fmaf(ry, sW1[1][j], rz * sW1[2][j]));
            const float r1 = fmaf(rx, sW1[0][j + 1],
                             fmaf(ry, sW1[1][j + 1], rz * sW1[2][j + 1]));
            R[k] = pack2(r0, r1);
            A[k] = pack2(sA[j], sA[j + 1]);
            W[k] = pack2(sW2[j], sW2[j + 1]);
        }

        // branchless coarse march: bitmask of free->occupied crossings
        unsigned mask = 0u;
        float zprev = occ_z2(NEARV, R, A, W, b2v);  // t=0 -> d=NEAR
#pragma unroll 1
        for (int i = 1; i < NSTEPS; i++) {
            const float t = (float)i * stepc;
            const float dcur = fmaf(far, t, NEARV * (1.0f - t));
            const float z = occ_z2(dcur, R, A, W, b2v);
            const bool cross = (zprev < 0.0f) && (z >= 0.0f);
            mask |= (cross ? 1u : 0u) << (i - 1);
            zprev = z;
        }

        // secant refinement, run unconditionally (warp-converged shfls);
        // results for unfound/miss/invalid rays are discarded below.
        const int idx = mask ? (__ffs(mask) - 1) : 0;
        const float tl = (float)idx * stepc;
        const float th = (float)(idx + 1) * stepc;
        float dl = fmaf(far, tl, NEARV * (1.0f - tl));
        float dh = fmaf(far, th, NEARV * (1.0f - th));
        float fl = sigmoidf_(occ_z2(dl, R, A, W, b2v)) - 0.5f;
        float fh = sigmoidf_(occ_z2(dh, R, A, W, b2v)) - 0.5f;

#pragma unroll 1
        for (int sit = 0; sit < NSECANT; sit++) {
            float den = fh - fl;
            if (fabsf(den) < EPSV) den = EPSV;
            const float dm = dl - __fdividef(fl * (dh - dl), den);
            const float fm = sigmoidf_(occ_z2(dm, R, A, W, b2v)) - 0.5f;
            if (fm < 0.0f) { dl = dm; fl = fm; }
            else           { dh = dm; fh = fm; }
        }
        float den = fh - fl;
        if (fabsf(den) < EPSV) den = EPSV;
        const float dmid = dl - __fdividef(fl * (dh - dl), den);
        const float osurf = sigmoidf_(occ_z2(dmid, R, A, W, b2v));

        const bool found = (mask != 0u) && hit;
        if (valid && half == 0) {
            out[p]     = found ? dmid  : 0.0f;
            out[P + p] = found ? osurf : 0.0f;
        }
    }
}

extern "C" void kernel_launch(void* const* d_in, const int* in_sizes, int n_in,
                              void* d_out, int out_size)
{
    const float* cam  = (const float*)d_in[0];
    const float* dirs = (const float*)d_in[1];
    const float* W1   = (const float*)d_in[2];
    const float* b1   = (const float*)d_in[3];
    const float* W2   = (const float*)d_in[4];
    const float* b2   = (const float*)d_in[5];
    float* out = (float*)d_out;

    const int P = in_sizes[1] / 3;
    const int threads = 128;
    int blocks = NBLK;
    const int maxb = (2 * P + threads - 1) / threads;  // 2 lanes per ray
    if (blocks > maxb) blocks = maxb;
    if (blocks < 1) blocks = 1;
    unisurf_kernel<<<blocks, threads>>>(cam, dirs, W1, b1, W2, b2, out, P);
}

// round 6
// speedup vs baseline: 1.6065x; 1.6065x over previous
#include <cuda_runtime.h>

// UniSURF-style renderer: per-ray sphere intersect + 32-step occupancy march
// + 8 secant iterations on a tiny MLP (3 -> 32 -> 1). One ray per thread.
//
//   occ logit z(d) = b2 + sum_j relu(A_j + d*R_j) * W2_j
//     A_j = cam.W1_j + b1_j (per-launch), R_j = ray.W1_j (per-ray regs)
//   March uses only sign(z); packed fp32x2 FMAs; branchless crossing bitmask;
//   march evals processed TWO AT A TIME (occ_z_dual, 4 indep acc chains) for
//   ILP; 64-thread blocks x 1024 = exactly 2 rays/thread (zero quantization).

#define HID     32
#define NPAIR   16
#define NSTEPS  32
#define NSECANT 8
#define NEARV   0.5f
#define EPSV    1e-6f
#define THREADS 64
#define NBLK    1024

typedef unsigned long long ull;

__device__ __forceinline__ ull pack2(float x, float y) {
    ull r;
    asm("mov.b64 %0, {%1, %2};" : "=l"(r) : "f"(x), "f"(y));
    return r;
}

__device__ __forceinline__ void unpack2(ull v, float& x, float& y) {
    asm("mov.b64 {%0, %1}, %2;" : "=f"(x), "=f"(y) : "l"(v));
}

// one hidden-unit pair: acc += relu(A + d*R) * W   (packed fp32x2)
__device__ __forceinline__ ull pair_step(ull dd, ull R, ull A, ull W, ull acc) {
    ull x;
    asm("fma.rn.f32x2 %0, %1, %2, %3;" : "=l"(x) : "l"(dd), "l"(R), "l"(A));
    float x0, x1;
    unpack2(x, x0, x1);
    x0 = fmaxf(x0, 0.0f);
    x1 = fmaxf(x1, 0.0f);
    ull h = pack2(x0, x1);
    ull out;
    asm("fma.rn.f32x2 %0, %1, %2, %3;" : "=l"(out) : "l"(h), "l"(W), "l"(acc));
    return out;
}

__device__ __forceinline__ ull dup2(float d) {
    ull dd;
    asm("mov.b64 %0, {%1, %1};" : "=l"(dd) : "f"(d));
    return dd;
}

__device__ __forceinline__ float reduce4(ull a0, ull a1, float b2v) {
    ull s;
    asm("add.rn.f32x2 %0, %1, %2;" : "=l"(s) : "l"(a0), "l"(a1));
    float sx, sy;
    unpack2(s, sx, sy);
    return b2v + (sx + sy);
}

// single eval, 4 independent chains (used in secant: latency-tolerant enough)
__device__ __forceinline__ float occ_z(float d, const ull* R, const ull* A,
                                       const ull* W, float b2v) {
    const ull dd = dup2(d);
    ull a0 = 0ull, a1 = 0ull, a2 = 0ull, a3 = 0ull;
#pragma unroll
    for (int k = 0; k < NPAIR; k += 4) {
        a0 = pair_step(dd, R[k + 0], A[k + 0], W[k + 0], a0);
        a1 = pair_step(dd, R[k + 1], A[k + 1], W[k + 1], a1);
        a2 = pair_step(dd, R[k + 2], A[k + 2], W[k + 2], a2);
        a3 = pair_step(dd, R[k + 3], A[k + 3], W[k + 3], a3);
    }
    ull s01, s23;
    asm("add.rn.f32x2 %0, %1, %2;" : "=l"(s01) : "l"(a0), "l"(a1));
    asm("add.rn.f32x2 %0, %1, %2;" : "=l"(s23) : "l"(a2), "l"(a3));
    return reduce4(s01, s23, b2v);
}

// dual eval: z(da) and z(db) together, 4 independent chains of length 8.
__device__ __forceinline__ void occ_z_dual(float da, float db,
                                           const ull* R, const ull* A,
                                           const ull* W, float b2v,
                                           float& za, float& zb) {
    const ull dda = dup2(da);
    const ull ddb = dup2(db);
    ull a0 = 0ull, a1 = 0ull, b0 = 0ull, b1 = 0ull;
#pragma unroll
    for (int k = 0; k < NPAIR; k += 2) {
        a0 = pair_step(dda, R[k + 0], A[k + 0], W[k + 0], a0);
        b0 = pair_step(ddb, R[k + 0], A[k + 0], W[k + 0], b0);
        a1 = pair_step(dda, R[k + 1], A[k + 1], W[k + 1], a1);
        b1 = pair_step(ddb, R[k + 1], A[k + 1], W[k + 1], b1);
    }
    za = reduce4(a0, a1, b2v);
    zb = reduce4(b0, b1, b2v);
}

__device__ __forceinline__ float sigmoidf_(float z) {
    return 1.0f / (1.0f + __expf(-z));
}

__global__ void __launch_bounds__(THREADS, 8) unisurf_kernel(
    const float* __restrict__ cam, const float* __restrict__ dirs,
    const float* __restrict__ W1, const float* __restrict__ b1,
    const float* __restrict__ W2, const float* __restrict__ b2,
    float* __restrict__ out, int P)
{
    __shared__ float sW1[3][HID];
    __shared__ float sA[HID];
    __shared__ float sW2[HID];
    __shared__ float sMisc[5];  // cam0..2, b2, |cam|^2

    const int tid = threadIdx.x;
    if (tid < HID) {
        const float c0 = cam[0], c1 = cam[1], c2 = cam[2];
        const float w0 = W1[tid], w1 = W1[HID + tid], w2 = W1[2 * HID + tid];
        sW1[0][tid] = w0;
        sW1[1][tid] = w1;
        sW1[2][tid] = w2;
        sA[tid] = fmaf(c0, w0, fmaf(c1, w1, fmaf(c2, w2, b1[tid])));
        sW2[tid] = W2[tid];
        if (tid == 0) {
            sMisc[0] = c0; sMisc[1] = c1; sMisc[2] = c2;
            sMisc[3] = b2[0];
            sMisc[4] = c0 * c0 + c1 * c1 + c2 * c2;
        }
    }
    __syncthreads();

    const float c0 = sMisc[0], c1 = sMisc[1], c2 = sMisc[2];
    const float b2v = sMisc[3], cc = sMisc[4];
    const float stepc = 1.0f / (float)(NSTEPS - 1);

    const int g = blockIdx.x * THREADS + tid;
    const int stride = gridDim.x * THREADS;   // 65536 -> exactly 2 rays/thread

    for (int p = g; p < P; p += stride) {
        const float dx = dirs[3 * p + 0];
        const float dy = dirs[3 * p + 1];
        const float dz = dirs[3 * p + 2];
        const float invn = rsqrtf(dx * dx + dy * dy + dz * dz);
        const float rx = dx * invn, ry = dy * invn, rz = dz * invn;

        const float rcd = rx * c0 + ry * c1 + rz * c2;
        const float under = rcd * rcd - (cc - 1.0f);   // radius = 1
        const bool hit = under > 0.0f;
        const float s = sqrtf(fmaxf(under, 0.0f));
        const float far = fmaxf(s - rcd, NEARV + EPSV);

        // per-ray MLP operands, packed as fp32x2 pairs
        ull R[NPAIR], A[NPAIR], W[NPAIR];
#pragma unroll
        for (int k = 0; k < NPAIR; k++) {
            const int j = 2 * k;
            const float r0 = fmaf(rx, sW1[0][j],
                             fmaf(ry, sW1[1][j], rz * sW1[2][j]));
            const float r1 = fmaf(rx, sW1[0][j + 1],
                             fmaf(ry, sW1[1][j + 1], rz * sW1[2][j + 1]));
            R[k] = pack2(r0, r1);
            A[k] = pack2(sA[j], sA[j + 1]);
            W[k] = pack2(sW2[j], sW2[j + 1]);
        }

        // branchless coarse march, two evals at a time
        unsigned mask = 0u;
        float zprev = occ_z(NEARV, R, A, W, b2v);   // i=0 -> d=NEAR exactly
#pragma unroll 1
        for (int i = 1; i <= NSTEPS - 3; i += 2) {  // i = 1,3,...,29
            const float ta = (float)i * stepc;
            const float tb = (float)(i + 1) * stepc;
            const float da = fmaf(far, ta, NEARV * (1.0f - ta));
            const float db = fmaf(far, tb, NEARV * (1.0f - tb));
            float za, zb;
            occ_z_dual(da, db, R, A, W, b2v, za, zb);
            mask |= ((zprev < 0.0f) && (za >= 0.0f) ? 1u : 0u) << (i - 1);
            mask |= ((za < 0.0f) && (zb >= 0.0f) ? 1u : 0u) << i;
            zprev = zb;
        }
        {   // final eval i = 31
            const float t = (float)(NSTEPS - 1) * stepc;
            const float dcur = fmaf(far, t, NEARV * (1.0f - t));
            const float z = occ_z(dcur, R, A, W, b2v);
            mask |= ((zprev < 0.0f) && (z >= 0.0f) ? 1u : 0u) << (NSTEPS - 2);
        }

        float dpred = 0.0f, osurf = 0.0f;
        const bool found = (mask != 0u) && hit;

        if (found) {
            const int idx = __ffs(mask) - 1;   // first crossing segment
            const float tl = (float)idx * stepc;
            const float th = (float)(idx + 1) * stepc;
            float dl = fmaf(far, tl, NEARV * (1.0f - tl));
            float dh = fmaf(far, th, NEARV * (1.0f - th));
            float zl, zh;
            occ_z_dual(dl, dh, R, A, W, b2v, zl, zh);
            float fl = sigmoidf_(zl) - 0.5f;
            float fh = sigmoidf_(zh) - 0.5f;

#pragma unroll 1
            for (int it = 0; it < NSECANT; it++) {
                float den = fh - fl;
                if (fabsf(den) < EPSV) den = EPSV;
                const float dm = dl - __fdividef(fl * (dh - dl), den);
                const float fm = sigmoidf_(occ_z(dm, R, A, W, b2v)) - 0.5f;
                if (fm < 0.0f) { dl = dm; fl = fm; }
                else           { dh = dm; fh = fm; }
            }
            float den = fh - fl;
            if (fabsf(den) < EPSV) den = EPSV;
            dpred = dl - __fdividef(fl * (dh - dl), den);
            osurf = sigmoidf_(occ_z(dpred, R, A, W, b2v));
        }

        out[p] = dpred;
        out[P + p] = osurf;
    }
}

extern "C" void kernel_launch(void* const* d_in, const int* in_sizes, int n_in,
                              void* d_out, int out_size)
{
    const float* cam  = (const float*)d_in[0];
    const float* dirs = (const float*)d_in[1];
    const float* W1   = (const float*)d_in[2];
    const float* b1   = (const float*)d_in[3];
    const float* W2   = (const float*)d_in[4];
    const float* b2   = (const float*)d_in[5];
    float* out = (float*)d_out;

    const int P = in_sizes[1] / 3;
    int blocks = NBLK;
    const int maxb = (P + THREADS - 1) / THREADS;
    if (blocks > maxb) blocks = maxb;
    if (blocks < 1) blocks = 1;
    unisurf_kernel<<<blocks, THREADS>>>(cam, dirs, W1, b1, W2, b2, out, P);
}

// round 8
// speedup vs baseline: 1.6444x; 1.0236x over previous
#include <cuda_runtime.h>

// UniSURF-style renderer: per-ray sphere intersect + 32-step occupancy march
// + 8 secant iterations on a tiny MLP (3 -> 32 -> 1). One ray per thread.
//
//   occ logit z(d) = b2 + sum_j relu(A_j + d*R_j) * W2_j
//     A_j = cam.W1_j + b1_j (per-launch), R_j = ray.W1_j (per-ray regs)
//   March uses only sign(z); packed fp32x2 FMAs; dual-eval (4 indep chains);
//   march z-values cached in smem (secant brackets = 2 LDS, not a re-eval);
//   incremental d stepping; predicated first-crossing capture;
//   64-thread blocks x 1024 = exactly 2 rays/thread on P=131072.

#define HID     32
#define NPAIR   16
#define NSTEPS  32
#define NSECANT 8
#define NEARV   0.5f
#define EPSV    1e-6f
#define THREADS 64
#define NBLK    1024

typedef unsigned long long ull;

__device__ __forceinline__ ull pack2(float x, float y) {
    ull r;
    asm("mov.b64 %0, {%1, %2};" : "=l"(r) : "f"(x), "f"(y));
    return r;
}

__device__ __forceinline__ void unpack2(ull v, float& x, float& y) {
    asm("mov.b64 {%0, %1}, %2;" : "=f"(x), "=f"(y) : "l"(v));
}

// one hidden-unit pair: acc += relu(A + d*R) * W   (packed fp32x2)
__device__ __forceinline__ ull pair_step(ull dd, ull R, ull A, ull W, ull acc) {
    ull x;
    asm("fma.rn.f32x2 %0, %1, %2, %3;" : "=l"(x) : "l"(dd), "l"(R), "l"(A));
    float x0, x1;
    unpack2(x, x0, x1);
    x0 = fmaxf(x0, 0.0f);
    x1 = fmaxf(x1, 0.0f);
    ull h = pack2(x0, x1);
    ull out;
    asm("fma.rn.f32x2 %0, %1, %2, %3;" : "=l"(out) : "l"(h), "l"(W), "l"(acc));
    return out;
}

__device__ __forceinline__ ull dup2(float d) {
    ull dd;
    asm("mov.b64 %0, {%1, %1};" : "=l"(dd) : "f"(d));
    return dd;
}

__device__ __forceinline__ float reduce4(ull a0, ull a1, float b2v) {
    ull s;
    asm("add.rn.f32x2 %0, %1, %2;" : "=l"(s) : "l"(a0), "l"(a1));
    float sx, sy;
    unpack2(s, sx, sy);
    return b2v + (sx + sy);
}

// single eval, 4 independent chains
__device__ __forceinline__ float occ_z(float d, const ull* R, const ull* A,
                                       const ull* W, float b2v) {
    const ull dd = dup2(d);
    ull a0 = 0ull, a1 = 0ull, a2 = 0ull, a3 = 0ull;
#pragma unroll
    for (int k = 0; k < NPAIR; k += 4) {
        a0 = pair_step(dd, R[k + 0], A[k + 0], W[k + 0], a0);
        a1 = pair_step(dd, R[k + 1], A[k + 1], W[k + 1], a1);
        a2 = pair_step(dd, R[k + 2], A[k + 2], W[k + 2], a2);
        a3 = pair_step(dd, R[k + 3], A[k + 3], W[k + 3], a3);
    }
    ull s01, s23;
    asm("add.rn.f32x2 %0, %1, %2;" : "=l"(s01) : "l"(a0), "l"(a1));
    asm("add.rn.f32x2 %0, %1, %2;" : "=l"(s23) : "l"(a2), "l"(a3));
    return reduce4(s01, s23, b2v);
}

// dual eval: z(da) and z(db) together, 4 independent chains of length 8.
__device__ __forceinline__ void occ_z_dual(float da, float db,
                                           const ull* R, const ull* A,
                                           const ull* W, float b2v,
                                           float& za, float& zb) {
    const ull dda = dup2(da);
    const ull ddb = dup2(db);
    ull a0 = 0ull, a1 = 0ull, b0 = 0ull, b1 = 0ull;
#pragma unroll
    for (int k = 0; k < NPAIR; k += 2) {
        a0 = pair_step(dda, R[k + 0], A[k + 0], W[k + 0], a0);
        b0 = pair_step(ddb, R[k + 0], A[k + 0], W[k + 0], b0);
        a1 = pair_step(dda, R[k + 1], A[k + 1], W[k + 1], a1);
        b1 = pair_step(ddb, R[k + 1], A[k + 1], W[k + 1], b1);
    }
    za = reduce4(a0, a1, b2v);
    zb = reduce4(b0, b1, b2v);
}

__device__ __forceinline__ float sigmoidf_(float z) {
    return 1.0f / (1.0f + __expf(-z));
}

__global__ void __launch_bounds__(THREADS, 8) unisurf_kernel(
    const float* __restrict__ cam, const float* __restrict__ dirs,
    const float* __restrict__ W1, const float* __restrict__ b1,
    const float* __restrict__ W2, const float* __restrict__ b2,
    float* __restrict__ out, int P)
{
    __shared__ float sW1[3][HID];
    __shared__ float sA[HID];
    __shared__ float sW2[HID];
    __shared__ float sMisc[5];              // cam0..2, b2, |cam|^2
    __shared__ float zbuf[NSTEPS][THREADS]; // march z cache (per thread)

    const int tid = threadIdx.x;
    if (tid < HID) {
        const float c0 = cam[0], c1 = cam[1], c2 = cam[2];
        const float w0 = W1[tid], w1 = W1[HID + tid], w2 = W1[2 * HID + tid];
        sW1[0][tid] = w0;
        sW1[1][tid] = w1;
        sW1[2][tid] = w2;
        sA[tid] = fmaf(c0, w0, fmaf(c1, w1, fmaf(c2, w2, b1[tid])));
        sW2[tid] = W2[tid];
        if (tid == 0) {
            sMisc[0] = c0; sMisc[1] = c1; sMisc[2] = c2;
            sMisc[3] = b2[0];
            sMisc[4] = c0 * c0 + c1 * c1 + c2 * c2;
        }
    }
    __syncthreads();

    const float c0 = sMisc[0], c1 = sMisc[1], c2 = sMisc[2];
    const float b2v = sMisc[3], cc = sMisc[4];
    const float stepc = 1.0f / (float)(NSTEPS - 1);

    const int g = blockIdx.x * THREADS + tid;
    const int stride = gridDim.x * THREADS;   // 65536 -> exactly 2 rays/thread

    for (int p = g; p < P; p += stride) {
        const float dx = dirs[3 * p + 0];
        const float dy = dirs[3 * p + 1];
        const float dz = dirs[3 * p + 2];
        const float invn = rsqrtf(dx * dx + dy * dy + dz * dz);
        const float rx = dx * invn, ry = dy * invn, rz = dz * invn;

        const float rcd = rx * c0 + ry * c1 + rz * c2;
        const float under = rcd * rcd - (cc - 1.0f);   // radius = 1
        const bool hit = under > 0.0f;
        const float s = sqrtf(fmaxf(under, 0.0f));
        const float far = fmaxf(s - rcd, NEARV + EPSV);
        const float stepd = (far - NEARV) * stepc;     // incremental step

        // per-ray MLP operands, packed as fp32x2 pairs
        ull R[NPAIR], A[NPAIR], W[NPAIR];
#pragma unroll
        for (int k = 0; k < NPAIR; k++) {
            const int j = 2 * k;
            const float r0 = fmaf(rx, sW1[0][j],
                             fmaf(ry, sW1[1][j], rz * sW1[2][j]));
            const float r1 = fmaf(rx, sW1[0][j + 1],
                             fmaf(ry, sW1[1][j + 1], rz * sW1[2][j + 1]));
            R[k] = pack2(r0, r1);
            A[k] = pack2(sA[j], sA[j + 1]);
            W[k] = pack2(sW2[j], sW2[j + 1]);
        }

        // coarse march, two evals at a time; cache z in smem; capture first
        // free->occupied crossing (earliest segment) with predicated selects.
        int  idx = 0;
        bool found = false;
        float zprev = occ_z(NEARV, R, A, W, b2v);   // sample 0 (d = NEAR)
        zbuf[0][tid] = zprev;
        float d = NEARV;
#pragma unroll 3
        for (int i = 1; i <= NSTEPS - 3; i += 2) {  // i = 1,3,...,29
            const float da = d + stepd;
            const float db = da + stepd;
            float za, zb;
            occ_z_dual(da, db, R, A, W, b2v, za, zb);
            zbuf[i][tid] = za;
            zbuf[i + 1][tid] = zb;
            const bool ca = (zprev < 0.0f) && (za >= 0.0f);
            const bool cb = (za < 0.0f) && (zb >= 0.0f);
            idx = (!found && ca) ? (i - 1) : idx;
            found |= ca;
            idx = (!found && cb) ? i : idx;
            found |= cb;
            zprev = zb;
            d = db;
        }
        {   // final sample i = 31
            const float dcur = d + stepd;
            const float z = occ_z(dcur, R, A, W, b2v);
            zbuf[NSTEPS - 1][tid] = z;
            const bool cl = (zprev < 0.0f) && (z >= 0.0f);
            idx = (!found && cl) ? (NSTEPS - 2) : idx;
            found |= cl;
        }

        float dpred = 0.0f, osurf = 0.0f;
        const bool ok = found && hit;

        if (ok) {
            // brackets via the exact reference formula; z from the cache
            const float tl = (float)idx * stepc;
            const float th = (float)(idx + 1) * stepc;
            float dl = fmaf(far, tl, NEARV * (1.0f - tl));
            float dh = fmaf(far, th, NEARV * (1.0f - th));
            float fl = sigmoidf_(zbuf[idx][tid]) - 0.5f;
            float fh = sigmoidf_(zbuf[idx + 1][tid]) - 0.5f;

#pragma unroll 1
            for (int it = 0; it < NSECANT; it++) {
                float den = fh - fl;
                if (fabsf(den) < EPSV) den = EPSV;
                const float dm = dl - __fdividef(fl * (dh - dl), den);
                const float fm = sigmoidf_(occ_z(dm, R, A, W, b2v)) - 0.5f;
                if (fm < 0.0f) { dl = dm; fl = fm; }
                else           { dh = dm; fh = fm; }
            }
            float den = fh - fl;
            if (fabsf(den) < EPSV) den = EPSV;
            dpred = dl - __fdividef(fl * (dh - dl), den);
            osurf = sigmoidf_(occ_z(dpred, R, A, W, b2v));
        }

        out[p] = dpred;
        out[P + p] = osurf;
    }
}

extern "C" void kernel_launch(void* const* d_in, const int* in_sizes, int n_in,
                              void* d_out, int out_size)
{
    const float* cam  = (const float*)d_in[0];
    const float* dirs = (const float*)d_in[1];
    const float* W1   = (const float*)d_in[2];
    const float* b1   = (const float*)d_in[3];
    const float* W2   = (const float*)d_in[4];
    const float* b2   = (const float*)d_in[5];
    float* out = (float*)d_out;

    const int P = in_sizes[1] / 3;
    int blocks = NBLK;
    const int maxb = (P + THREADS - 1) / THREADS;
    if (blocks > maxb) blocks = maxb;
    if (blocks < 1) blocks = 1;
    unisurf_kernel<<<blocks, THREADS>>>(cam, dirs, W1, b1, W2, b2, out, P);
}